// round 1
// baseline (speedup 1.0000x reference)
#include <cuda_runtime.h>
#include <math.h>

// Problem constants (match reference)
#define BB 16
#define NN 512
#define DD 256
#define HH 8
#define DKK 32

// Scratch (device globals; no allocation allowed in kernel_launch)
__device__ __align__(128) float g_Q[BB * NN * DD];
__device__ __align__(128) float g_K[BB * NN * DD];
__device__ __align__(128) float g_V[BB * NN * DD];
__device__ __align__(128) float g_X[BB * NN * DD];
__device__ __align__(128) float g_G[BB * NN * NN];

// ----------------------------------------------------------------------------
// GEMM: Y[m,n] = sum_k X[m,k] * W[n,k] + bias[n]   (X:[M,256] row-major, W:[256,256])
// Tile 64x64, K-tile 16, 256 threads, 4x4 outputs/thread.
// src_sel: 0 -> use Xin param, 1 -> use g_X
// dst_sel: 0 -> g_Q, 1 -> g_K, 2 -> g_V, 3 -> Yext
// ----------------------------------------------------------------------------
__global__ void __launch_bounds__(256) gemm_nt_bias(
    const float* __restrict__ Xin, const float* __restrict__ W,
    const float* __restrict__ bias, float* __restrict__ Yext,
    int src_sel, int dst_sel)
{
    __shared__ float Xs[64][17];
    __shared__ float Wsm[64][17];

    const float* X = (src_sel == 1) ? g_X : Xin;
    float* Y;
    switch (dst_sel) {
        case 0: Y = g_Q; break;
        case 1: Y = g_K; break;
        case 2: Y = g_V; break;
        default: Y = Yext; break;
    }

    const int tid = threadIdx.x;
    const int tx = tid & 15;        // 0..15 -> n micro
    const int ty = tid >> 4;        // 0..15 -> m micro
    const int m0 = blockIdx.x * 64;
    const int n0 = blockIdx.y * 64;

    const int r = tid >> 2;         // 0..63  (load row)
    const int c = (tid & 3) << 2;   // 0,4,8,12 (load col group)

    float acc[4][4];
#pragma unroll
    for (int i = 0; i < 4; i++)
#pragma unroll
        for (int j = 0; j < 4; j++) acc[i][j] = 0.f;

    for (int kt = 0; kt < DD; kt += 16) {
        float4 xv = *(const float4*)&X[(size_t)(m0 + r) * DD + kt + c];
        float4 wv = *(const float4*)&W[(size_t)(n0 + r) * DD + kt + c];
        __syncthreads();   // previous iteration's reads complete
        Xs[r][c + 0] = xv.x; Xs[r][c + 1] = xv.y; Xs[r][c + 2] = xv.z; Xs[r][c + 3] = xv.w;
        Wsm[r][c + 0] = wv.x; Wsm[r][c + 1] = wv.y; Wsm[r][c + 2] = wv.z; Wsm[r][c + 3] = wv.w;
        __syncthreads();
#pragma unroll
        for (int kk = 0; kk < 16; kk++) {
            float xr[4], wr[4];
#pragma unroll
            for (int i = 0; i < 4; i++) {
                xr[i] = Xs[ty * 4 + i][kk];
                wr[i] = Wsm[tx * 4 + i][kk];
            }
#pragma unroll
            for (int i = 0; i < 4; i++)
#pragma unroll
                for (int j = 0; j < 4; j++)
                    acc[i][j] += xr[i] * wr[j];
        }
    }

#pragma unroll
    for (int i = 0; i < 4; i++) {
#pragma unroll
        for (int j = 0; j < 4; j++) {
            int n = n0 + tx * 4 + j;
            Y[(size_t)(m0 + ty * 4 + i) * DD + n] = acc[i][j] + bias[n];
        }
    }
}

// ----------------------------------------------------------------------------
// G[b,q,k] = 0.3 * softmax_k( valid ? -dist : -inf ) + 0.4 * adj / (rowsum(adj)+eps)
// One block (256 threads) per (b,q) row; each thread handles 2 columns.
// ----------------------------------------------------------------------------
__global__ void __launch_bounds__(256) build_G(
    const float* __restrict__ dist, const float* __restrict__ adj,
    const int* __restrict__ mask)
{
    const int q = blockIdx.x;
    const int b = blockIdx.y;
    const int t = threadIdx.x;
    const int lane = t & 31, warp = t >> 5;
    const size_t row = ((size_t)b * NN + q) * NN;

    float d0 = dist[row + t], d1 = dist[row + t + 256];
    float a0 = adj[row + t],  a1 = adj[row + t + 256];
    int v0 = mask[b * NN + t] != 0;
    int v1 = mask[b * NN + t + 256] != 0;
    const float NINF = -__int_as_float(0x7f800000);
    float s0 = v0 ? -d0 : NINF;
    float s1 = v1 ? -d1 : NINF;

    __shared__ float red[8];
    __shared__ float red2[8];

    // row max of masked (-dist)
    float m = fmaxf(s0, s1);
#pragma unroll
    for (int o = 16; o > 0; o >>= 1) m = fmaxf(m, __shfl_xor_sync(0xffffffffu, m, o));
    if (lane == 0) red[warp] = m;
    __syncthreads();
    float mall = red[0];
#pragma unroll
    for (int i = 1; i < 8; i++) mall = fmaxf(mall, red[i]);
    __syncthreads();

    float e0 = v0 ? __expf(s0 - mall) : 0.f;
    float e1 = v1 ? __expf(s1 - mall) : 0.f;
    float se = e0 + e1;
    float sa = a0 + a1;
#pragma unroll
    for (int o = 16; o > 0; o >>= 1) {
        se += __shfl_xor_sync(0xffffffffu, se, o);
        sa += __shfl_xor_sync(0xffffffffu, sa, o);
    }
    if (lane == 0) { red[warp] = se; red2[warp] = sa; }
    __syncthreads();
    float tse = 0.f, tsa = 0.f;
#pragma unroll
    for (int i = 0; i < 8; i++) { tse += red[i]; tsa += red2[i]; }

    float invd = 0.3f / tse;
    float inva = 0.4f / (tsa + 1e-6f);
    g_G[row + t]       = e0 * invd + a0 * inva;
    g_G[row + t + 256] = e1 * invd + a1 * inva;
}

// ----------------------------------------------------------------------------
// Fused attention per (q-tile 32, head, batch):
//   S = Q_h K_h^T / sqrt(32)  -> mask -> softmax (registers, warp shuffles)
//   W = 0.3*P + G             -> smem
//   X_h = W @ V_h
// Block: 256 threads = 8 warps; warp w owns q-rows w*4..w*4+3; each lane
// holds 16 key slots per row (k = (j>>1)*64 + (j&1)*32 + lane).
// ----------------------------------------------------------------------------
#define ATTN_SMEM ((32 * 512 + 32 * 33 + 64 * 33) * 4)

__global__ void __launch_bounds__(256) attn_kernel(const int* __restrict__ mask)
{
    extern __shared__ float sm[];
    float* Wsh = sm;                    // [32][512] blended weights
    float* Qs  = sm + 32 * 512;         // [32][33]
    float* KVs = Qs + 32 * 33;          // [64][33]

    const int qt = blockIdx.x, h = blockIdx.y, b = blockIdx.z;
    const int tid = threadIdx.x;
    const int lane = tid & 31, warp = tid >> 5;
    const int q0 = qt * 32;
    const size_t baseQ = ((size_t)b * NN + q0) * DD + h * DKK;

    // Load Q tile (32x32)
    {
        int r = tid >> 3;
        int c = (tid & 7) << 2;
        float4 v = *(const float4*)&g_Q[baseQ + (size_t)r * DD + c];
        Qs[r * 33 + c + 0] = v.x; Qs[r * 33 + c + 1] = v.y;
        Qs[r * 33 + c + 2] = v.z; Qs[r * 33 + c + 3] = v.w;
    }

    float S[4][16];
#pragma unroll
    for (int i = 0; i < 4; i++)
#pragma unroll
        for (int j = 0; j < 16; j++) S[i][j] = 0.f;

    // Phase 1: scores
    for (int t = 0; t < 8; t++) {
        __syncthreads();  // protects KVs reuse (and Qs on first iter)
#pragma unroll
        for (int it = 0; it < 2; it++) {
            int idx = tid + it * 256;
            int kr = idx >> 3;
            int kc = (idx & 7) << 2;
            float4 v = *(const float4*)&g_K[((size_t)(b * NN + t * 64 + kr)) * DD + h * DKK + kc];
            KVs[kr * 33 + kc + 0] = v.x; KVs[kr * 33 + kc + 1] = v.y;
            KVs[kr * 33 + kc + 2] = v.z; KVs[kr * 33 + kc + 3] = v.w;
        }
        __syncthreads();
#pragma unroll
        for (int dk = 0; dk < 32; dk++) {
            float k0 = KVs[lane * 33 + dk];
            float k1 = KVs[(lane + 32) * 33 + dk];
#pragma unroll
            for (int qi = 0; qi < 4; qi++) {
                float qv = Qs[(warp * 4 + qi) * 33 + dk];
                S[qi][2 * t]     += qv * k0;
                S[qi][2 * t + 1] += qv * k1;
            }
        }
    }

    // key-validity bits for this lane's 16 slots
    unsigned vb = 0;
#pragma unroll
    for (int j = 0; j < 16; j++) {
        int k = (j >> 1) * 64 + (j & 1) * 32 + lane;
        if (mask[b * NN + k] != 0) vb |= (1u << j);
    }

    const float scale = 0.17677669529663687f;  // 1/sqrt(32)
    const float NINF = -__int_as_float(0x7f800000);

#pragma unroll
    for (int qi = 0; qi < 4; qi++) {
        float m = NINF;
#pragma unroll
        for (int j = 0; j < 16; j++) {
            float v = S[qi][j] * scale;
            v = ((vb >> j) & 1u) ? v : -1e12f;
            S[qi][j] = v;
            m = fmaxf(m, v);
        }
#pragma unroll
        for (int o = 16; o > 0; o >>= 1) m = fmaxf(m, __shfl_xor_sync(0xffffffffu, m, o));
        float s = 0.f;
#pragma unroll
        for (int j = 0; j < 16; j++) {
            float e = __expf(S[qi][j] - m);
            S[qi][j] = e;
            s += e;
        }
#pragma unroll
        for (int o = 16; o > 0; o >>= 1) s += __shfl_xor_sync(0xffffffffu, s, o);
        float inv = 0.3f / s;

        const int qrow = warp * 4 + qi;
        const float* Grow = g_G + ((size_t)(b * NN + q0 + qrow)) * NN;
        float* Wrow = Wsh + qrow * 512;
#pragma unroll
        for (int j = 0; j < 16; j++) {
            int k = (j >> 1) * 64 + (j & 1) * 32 + lane;
            Wrow[k] = S[qi][j] * inv + Grow[k];
        }
    }
    __syncthreads();  // Wsh complete; KVs free

    // Phase 2: X_h = Wsh @ V_h   (thread: dk = lane, q-rows = warp*4+qi)
    float O[4] = {0.f, 0.f, 0.f, 0.f};
    for (int t = 0; t < 8; t++) {
#pragma unroll
        for (int it = 0; it < 2; it++) {
            int idx = tid + it * 256;
            int kr = idx >> 3;
            int kc = (idx & 7) << 2;
            float4 v = *(const float4*)&g_V[((size_t)(b * NN + t * 64 + kr)) * DD + h * DKK + kc];
            KVs[kr * 33 + kc + 0] = v.x; KVs[kr * 33 + kc + 1] = v.y;
            KVs[kr * 33 + kc + 2] = v.z; KVs[kr * 33 + kc + 3] = v.w;
        }
        __syncthreads();
#pragma unroll
        for (int kl = 0; kl < 64; kl++) {
            float vv = KVs[kl * 33 + lane];
            int k = t * 64 + kl;
#pragma unroll
            for (int qi = 0; qi < 4; qi++)
                O[qi] += Wsh[(warp * 4 + qi) * 512 + k] * vv;
        }
        __syncthreads();
    }

#pragma unroll
    for (int qi = 0; qi < 4; qi++)
        g_X[((size_t)(b * NN + q0 + warp * 4 + qi)) * DD + h * DKK + lane] = O[qi];
}

// ----------------------------------------------------------------------------
// Launch
// Inputs (metadata order): query, key, value, adj_matrix, distances_matrix,
// edges_att, mask, Wq, bq, Wk, bk, Wv, bv, Wo, bo
// ----------------------------------------------------------------------------
extern "C" void kernel_launch(void* const* d_in, const int* in_sizes, int n_in,
                              void* d_out, int out_size)
{
    (void)in_sizes; (void)n_in; (void)out_size;
    const float* query = (const float*)d_in[0];
    const float* key_  = (const float*)d_in[1];
    const float* value = (const float*)d_in[2];
    const float* adj   = (const float*)d_in[3];
    const float* dist  = (const float*)d_in[4];
    // d_in[5] = edges_att (unused)
    const int*   mask  = (const int*)d_in[6];
    const float* Wq = (const float*)d_in[7],  *bq = (const float*)d_in[8];
    const float* Wk = (const float*)d_in[9],  *bk = (const float*)d_in[10];
    const float* Wv = (const float*)d_in[11], *bv = (const float*)d_in[12];
    const float* Wo = (const float*)d_in[13], *bo = (const float*)d_in[14];
    float* out = (float*)d_out;

    cudaFuncSetAttribute(attn_kernel, cudaFuncAttributeMaxDynamicSharedMemorySize, ATTN_SMEM);

    dim3 gProj(128, 4);   // M=8192/64, N=256/64
    gemm_nt_bias<<<gProj, 256>>>(query, Wq, bq, nullptr, 0, 0);
    gemm_nt_bias<<<gProj, 256>>>(key_,  Wk, bk, nullptr, 0, 1);
    gemm_nt_bias<<<gProj, 256>>>(value, Wv, bv, nullptr, 0, 2);

    build_G<<<dim3(NN, BB), 256>>>(dist, adj, mask);

    attn_kernel<<<dim3(NN / 32, HH, BB), 256, ATTN_SMEM>>>(mask);

    gemm_nt_bias<<<gProj, 256>>>(nullptr, Wo, bo, out, 1, 3);
}

// round 2
// speedup vs baseline: 2.2992x; 2.2992x over previous
#include <cuda_runtime.h>

#define BB 16
#define NN 512
#define DD 256
#define HH 8
#define DKK 32

// Scratch (device globals; no allocation allowed)
__device__ __align__(128) float g_Q[BB * NN * DD];
__device__ __align__(128) float g_K[BB * NN * DD];
__device__ __align__(128) float g_V[BB * NN * DD];
__device__ __align__(128) float g_X[BB * NN * DD];
__device__ __align__(128) float g_G[BB * NN * NN];

// ---------------------------------------------------------------------------
// tf32 helpers
// ---------------------------------------------------------------------------
__device__ __forceinline__ unsigned f2tf(float x) {
    unsigned r;
    asm("cvt.rna.tf32.f32 %0, %1;" : "=r"(r) : "f"(x));
    return r;
}

__device__ __forceinline__ void mma8(float* c,
                                     unsigned a0, unsigned a1, unsigned a2, unsigned a3,
                                     unsigned b0, unsigned b1) {
    asm volatile(
        "mma.sync.aligned.m16n8k8.row.col.f32.tf32.tf32.f32 "
        "{%0,%1,%2,%3},{%4,%5,%6,%7},{%8,%9},{%0,%1,%2,%3};"
        : "+f"(c[0]), "+f"(c[1]), "+f"(c[2]), "+f"(c[3])
        : "r"(a0), "r"(a1), "r"(a2), "r"(a3), "r"(b0), "r"(b1));
}

// ---------------------------------------------------------------------------
// tf32 GEMM: Y[m,n] = sum_k X[m,k]*W[n,k] + bias[n]; M=8192, N=256, K=256
// Block tile 128x64, BK=32, 256 threads = 8 warps (4m x 2n), warp tile 32x32.
// ---------------------------------------------------------------------------
#define GBM 128
#define GBN 64
#define GBK 32
#define GLD (GBK + 4)   // pad 4 -> conflict-free fragment loads

__global__ void __launch_bounds__(256) gemm_tf32(
    const float* __restrict__ Xin, const float* __restrict__ W,
    const float* __restrict__ bias, float* __restrict__ Yext,
    int src_sel, int dst_sel)
{
    __shared__ unsigned Xs[GBM * GLD];
    __shared__ unsigned Ws[GBN * GLD];

    const float* X = src_sel ? g_X : Xin;
    float* Y;
    switch (dst_sel) {
        case 0: Y = g_Q; break;
        case 1: Y = g_K; break;
        case 2: Y = g_V; break;
        default: Y = Yext; break;
    }

    const int tid = threadIdx.x;
    const int warp = tid >> 5, lane = tid & 31;
    const int g = lane >> 2, tig = lane & 3;
    const int wm = warp >> 1, wn = warp & 1;
    const int m0 = blockIdx.x * GBM, n0 = blockIdx.y * GBN;

    float acc[2][4][4];
#pragma unroll
    for (int mt = 0; mt < 2; mt++)
#pragma unroll
        for (int nt = 0; nt < 4; nt++)
#pragma unroll
            for (int i = 0; i < 4; i++) acc[mt][nt][i] = 0.f;

    for (int kt = 0; kt < DD; kt += GBK) {
        float4 xv[4], wv[2];
#pragma unroll
        for (int i = 0; i < 4; i++) {
            int e = tid + 256 * i;
            xv[i] = *(const float4*)&X[(size_t)(m0 + (e >> 3)) * DD + kt + 4 * (e & 7)];
        }
#pragma unroll
        for (int i = 0; i < 2; i++) {
            int e = tid + 256 * i;
            wv[i] = *(const float4*)&W[(size_t)(n0 + (e >> 3)) * DD + kt + 4 * (e & 7)];
        }
        __syncthreads();
#pragma unroll
        for (int i = 0; i < 4; i++) {
            int e = tid + 256 * i;
            unsigned* p = &Xs[(e >> 3) * GLD + 4 * (e & 7)];
            p[0] = f2tf(xv[i].x); p[1] = f2tf(xv[i].y);
            p[2] = f2tf(xv[i].z); p[3] = f2tf(xv[i].w);
        }
#pragma unroll
        for (int i = 0; i < 2; i++) {
            int e = tid + 256 * i;
            unsigned* p = &Ws[(e >> 3) * GLD + 4 * (e & 7)];
            p[0] = f2tf(wv[i].x); p[1] = f2tf(wv[i].y);
            p[2] = f2tf(wv[i].z); p[3] = f2tf(wv[i].w);
        }
        __syncthreads();

#pragma unroll
        for (int k8 = 0; k8 < 4; k8++) {
            int k0 = k8 * 8;
            unsigned a[2][4];
#pragma unroll
            for (int mt = 0; mt < 2; mt++) {
                int r = wm * 32 + mt * 16;
                a[mt][0] = Xs[(r + g) * GLD + k0 + tig];
                a[mt][1] = Xs[(r + g + 8) * GLD + k0 + tig];
                a[mt][2] = Xs[(r + g) * GLD + k0 + tig + 4];
                a[mt][3] = Xs[(r + g + 8) * GLD + k0 + tig + 4];
            }
#pragma unroll
            for (int nt = 0; nt < 4; nt++) {
                int cb = wn * 32 + nt * 8;
                unsigned b0 = Ws[(cb + g) * GLD + k0 + tig];
                unsigned b1 = Ws[(cb + g) * GLD + k0 + tig + 4];
                mma8(acc[0][nt], a[0][0], a[0][1], a[0][2], a[0][3], b0, b1);
                mma8(acc[1][nt], a[1][0], a[1][1], a[1][2], a[1][3], b0, b1);
            }
        }
        __syncthreads();
    }

#pragma unroll
    for (int mt = 0; mt < 2; mt++) {
        int row = m0 + wm * 32 + mt * 16 + g;
#pragma unroll
        for (int nt = 0; nt < 4; nt++) {
            int col = n0 + wn * 32 + nt * 8 + 2 * tig;
            float b0 = bias[col], b1 = bias[col + 1];
            *(float2*)&Y[(size_t)row * DD + col] =
                make_float2(acc[mt][nt][0] + b0, acc[mt][nt][1] + b1);
            *(float2*)&Y[(size_t)(row + 8) * DD + col] =
                make_float2(acc[mt][nt][2] + b0, acc[mt][nt][3] + b1);
        }
    }
}

// ---------------------------------------------------------------------------
// G[b,q,k] = 0.3 * softmax_k(valid ? -dist : -inf) + 0.4 * adj/(rowsum+eps)
// ---------------------------------------------------------------------------
__global__ void __launch_bounds__(256) build_G(
    const float* __restrict__ dist, const float* __restrict__ adj,
    const int* __restrict__ mask)
{
    const int q = blockIdx.x, b = blockIdx.y;
    const int t = threadIdx.x;
    const int lane = t & 31, warp = t >> 5;
    const size_t row = ((size_t)b * NN + q) * NN;

    float d0 = dist[row + t], d1 = dist[row + t + 256];
    float a0 = adj[row + t], a1 = adj[row + t + 256];
    int v0 = mask[b * NN + t] != 0;
    int v1 = mask[b * NN + t + 256] != 0;
    const float NINF = -__int_as_float(0x7f800000);
    float s0 = v0 ? -d0 : NINF;
    float s1 = v1 ? -d1 : NINF;

    __shared__ float red[8], red2[8];

    float m = fmaxf(s0, s1);
#pragma unroll
    for (int o = 16; o > 0; o >>= 1) m = fmaxf(m, __shfl_xor_sync(0xffffffffu, m, o));
    if (lane == 0) red[warp] = m;
    __syncthreads();
    float mall = red[0];
#pragma unroll
    for (int i = 1; i < 8; i++) mall = fmaxf(mall, red[i]);
    __syncthreads();

    float e0 = v0 ? __expf(s0 - mall) : 0.f;
    float e1 = v1 ? __expf(s1 - mall) : 0.f;
    float se = e0 + e1, sa = a0 + a1;
#pragma unroll
    for (int o = 16; o > 0; o >>= 1) {
        se += __shfl_xor_sync(0xffffffffu, se, o);
        sa += __shfl_xor_sync(0xffffffffu, sa, o);
    }
    if (lane == 0) { red[warp] = se; red2[warp] = sa; }
    __syncthreads();
    float tse = 0.f, tsa = 0.f;
#pragma unroll
    for (int i = 0; i < 8; i++) { tse += red[i]; tsa += red2[i]; }

    float invd = 0.3f / tse;
    float inva = 0.4f / (tsa + 1e-6f);
    g_G[row + t]       = e0 * invd + a0 * inva;
    g_G[row + t + 256] = e1 * invd + a1 * inva;
}

// ---------------------------------------------------------------------------
// Fused attention (tensor cores). Block = (qtile=64, head, batch), 256 thr.
// Phase 1: S = Q K^T (mma, raw scores -> Wsh fp32 smem)
// Softmax + blend with G (tf32-converted in place)
// Phase 2: O = W V (mma, V fragments read transposed from smem)
// ---------------------------------------------------------------------------
#define QT 64
#define WLD (NN + 4)     // 516 (pad 4)
#define KLD (DKK + 4)    // 36

#define SM_KV (QT * WLD)              // word offsets
#define SM_Q  (SM_KV + NN * KLD)
#define SM_M  (SM_Q + QT * KLD)
#define SM_TOT (SM_M + NN)
#define ATT_SMEM (SM_TOT * 4)

__global__ void __launch_bounds__(256) attn_tc(const int* __restrict__ mask)
{
    extern __shared__ unsigned sm[];
    float* Wsh = (float*)sm;         // [64][516] raw scores, then tf32 weights
    unsigned* KVs = sm + SM_KV;      // [512][36] K then V (tf32)
    unsigned* Qs = sm + SM_Q;        // [64][36]  Q (tf32)
    float* msk = (float*)(sm + SM_M);

    const int qt = blockIdx.x, h = blockIdx.y, b = blockIdx.z;
    const int q0 = qt * QT;
    const int tid = threadIdx.x, warp = tid >> 5, lane = tid & 31;
    const int g = lane >> 2, tig = lane & 3;

    // Load Q tile (64x32) + mask
#pragma unroll
    for (int i = 0; i < 2; i++) {
        int e = tid + 256 * i;
        float4 v = *(const float4*)&g_Q[((size_t)(b * NN + q0 + (e >> 3))) * DD + h * DKK + 4 * (e & 7)];
        unsigned* p = &Qs[(e >> 3) * KLD + 4 * (e & 7)];
        p[0] = f2tf(v.x); p[1] = f2tf(v.y); p[2] = f2tf(v.z); p[3] = f2tf(v.w);
    }
#pragma unroll
    for (int i = 0; i < 2; i++) {
        int k = tid + 256 * i;
        msk[k] = (mask[b * NN + k] != 0) ? 0.f : 1.f;
    }
    // Load K (512x32)
#pragma unroll
    for (int i = 0; i < 16; i++) {
        int e = tid + 256 * i;
        float4 v = *(const float4*)&g_K[((size_t)(b * NN + (e >> 3))) * DD + h * DKK + 4 * (e & 7)];
        unsigned* p = &KVs[(e >> 3) * KLD + 4 * (e & 7)];
        p[0] = f2tf(v.x); p[1] = f2tf(v.y); p[2] = f2tf(v.z); p[3] = f2tf(v.w);
    }
    __syncthreads();

    // Phase 1: scores
    {
        const int wm = warp >> 1, wn = warp & 1;   // rows wm*16, keys wn*256
        unsigned a[4][4];
#pragma unroll
        for (int k8 = 0; k8 < 4; k8++) {
            int k0 = k8 * 8, r = wm * 16;
            a[k8][0] = Qs[(r + g) * KLD + k0 + tig];
            a[k8][1] = Qs[(r + g + 8) * KLD + k0 + tig];
            a[k8][2] = Qs[(r + g) * KLD + k0 + tig + 4];
            a[k8][3] = Qs[(r + g + 8) * KLD + k0 + tig + 4];
        }
#pragma unroll
        for (int nc = 0; nc < 4; nc++) {
            float acc[8][4];
#pragma unroll
            for (int nt = 0; nt < 8; nt++)
#pragma unroll
                for (int i = 0; i < 4; i++) acc[nt][i] = 0.f;
#pragma unroll
            for (int k8 = 0; k8 < 4; k8++) {
                int k0 = k8 * 8;
#pragma unroll
                for (int nt = 0; nt < 8; nt++) {
                    int key = wn * 256 + nc * 64 + nt * 8;
                    unsigned b0 = KVs[(key + g) * KLD + k0 + tig];
                    unsigned b1 = KVs[(key + g) * KLD + k0 + tig + 4];
                    mma8(acc[nt], a[k8][0], a[k8][1], a[k8][2], a[k8][3], b0, b1);
                }
            }
            int row = wm * 16 + g;
#pragma unroll
            for (int nt = 0; nt < 8; nt++) {
                int col = wn * 256 + nc * 64 + nt * 8 + 2 * tig;
                *(float2*)&Wsh[row * WLD + col] = make_float2(acc[nt][0], acc[nt][1]);
                *(float2*)&Wsh[(row + 8) * WLD + col] = make_float2(acc[nt][2], acc[nt][3]);
            }
        }
    }
    __syncthreads();

    // Load V into KVs (K no longer needed)
#pragma unroll
    for (int i = 0; i < 16; i++) {
        int e = tid + 256 * i;
        float4 v = *(const float4*)&g_V[((size_t)(b * NN + (e >> 3))) * DD + h * DKK + 4 * (e & 7)];
        unsigned* p = &KVs[(e >> 3) * KLD + 4 * (e & 7)];
        p[0] = f2tf(v.x); p[1] = f2tf(v.y); p[2] = f2tf(v.z); p[3] = f2tf(v.w);
    }

    // Softmax + blend (warp w handles rows w*8..w*8+7)
    const float scale = 0.17677669529663687f;  // 1/sqrt(32)
    for (int rr = 0; rr < 8; rr++) {
        int row = warp * 8 + rr;
        float v[16];
        float m = -3.4e38f;
#pragma unroll
        for (int j = 0; j < 16; j++) {
            int k = lane + 32 * j;
            float s = Wsh[row * WLD + k] * scale - 1e12f * msk[k];
            v[j] = s;
            m = fmaxf(m, s);
        }
#pragma unroll
        for (int o = 16; o > 0; o >>= 1) m = fmaxf(m, __shfl_xor_sync(0xffffffffu, m, o));
        float sum = 0.f;
#pragma unroll
        for (int j = 0; j < 16; j++) {
            float e = __expf(v[j] - m);
            v[j] = e;
            sum += e;
        }
#pragma unroll
        for (int o = 16; o > 0; o >>= 1) sum += __shfl_xor_sync(0xffffffffu, sum, o);
        float inv = 0.3f / sum;
        const float* Grow = g_G + ((size_t)(b * NN + q0 + row)) * NN;
#pragma unroll
        for (int j = 0; j < 16; j++) {
            int k = lane + 32 * j;
            float w = fmaf(v[j], inv, Grow[k]);
            ((unsigned*)Wsh)[row * WLD + k] = f2tf(w);
        }
    }
    __syncthreads();

    // Phase 2: O = W @ V
    {
        const int wm = warp >> 1, wn = warp & 1;
        const unsigned* W32 = (const unsigned*)Wsh;
        float o[2][4];
#pragma unroll
        for (int nt = 0; nt < 2; nt++)
#pragma unroll
            for (int i = 0; i < 4; i++) o[nt][i] = 0.f;

#pragma unroll 4
        for (int k0 = 0; k0 < NN; k0 += 8) {
            int r = wm * 16;
            unsigned a0 = W32[(r + g) * WLD + k0 + tig];
            unsigned a1 = W32[(r + g + 8) * WLD + k0 + tig];
            unsigned a2 = W32[(r + g) * WLD + k0 + tig + 4];
            unsigned a3 = W32[(r + g + 8) * WLD + k0 + tig + 4];
#pragma unroll
            for (int nt = 0; nt < 2; nt++) {
                int n = wn * 16 + nt * 8;
                unsigned b0 = KVs[(k0 + tig) * KLD + n + g];
                unsigned b1 = KVs[(k0 + tig + 4) * KLD + n + g];
                mma8(o[nt], a0, a1, a2, a3, b0, b1);
            }
        }
        int row = q0 + wm * 16 + g;
#pragma unroll
        for (int nt = 0; nt < 2; nt++) {
            int col = h * DKK + wn * 16 + nt * 8 + 2 * tig;
            *(float2*)&g_X[((size_t)(b * NN + row)) * DD + col] = make_float2(o[nt][0], o[nt][1]);
            *(float2*)&g_X[((size_t)(b * NN + row + 8)) * DD + col] = make_float2(o[nt][2], o[nt][3]);
        }
    }
}

// ---------------------------------------------------------------------------
// Launch. Inputs: query,key,value,adj,dist,edges_att,mask,Wq,bq,Wk,bk,Wv,bv,Wo,bo
// ---------------------------------------------------------------------------
extern "C" void kernel_launch(void* const* d_in, const int* in_sizes, int n_in,
                              void* d_out, int out_size)
{
    (void)in_sizes; (void)n_in; (void)out_size;
    const float* query = (const float*)d_in[0];
    const float* key_  = (const float*)d_in[1];
    const float* value = (const float*)d_in[2];
    const float* adj   = (const float*)d_in[3];
    const float* dist  = (const float*)d_in[4];
    const int*   mask  = (const int*)d_in[6];
    const float* Wq = (const float*)d_in[7],  *bq = (const float*)d_in[8];
    const float* Wk = (const float*)d_in[9],  *bk = (const float*)d_in[10];
    const float* Wv = (const float*)d_in[11], *bv = (const float*)d_in[12];
    const float* Wo = (const float*)d_in[13], *bo = (const float*)d_in[14];
    float* out = (float*)d_out;

    cudaFuncSetAttribute(attn_tc, cudaFuncAttributeMaxDynamicSharedMemorySize, ATT_SMEM);

    dim3 gProj(BB * NN / GBM, DD / GBN);   // (64, 4)
    gemm_tf32<<<gProj, 256>>>(query, Wq, bq, nullptr, 0, 0);
    gemm_tf32<<<gProj, 256>>>(key_,  Wk, bk, nullptr, 0, 1);
    gemm_tf32<<<gProj, 256>>>(value, Wv, bv, nullptr, 0, 2);

    build_G<<<dim3(NN, BB), 256>>>(dist, adj, mask);

    attn_tc<<<dim3(NN / QT, HH, BB), 256, ATT_SMEM>>>(mask);

    gemm_tf32<<<gProj, 256>>>(nullptr, Wo, bo, out, 1, 3);
}

// round 3
// speedup vs baseline: 2.5098x; 1.0916x over previous
#include <cuda_runtime.h>

#define BB 16
#define NN 512
#define DD 256
#define HH 8
#define DKK 32

// Scratch (device globals; no allocation allowed)
// g_Q/g_K/g_V hold tf32-rounded bit patterns (stored as float)
__device__ __align__(128) float g_Q[BB * NN * DD];
__device__ __align__(128) float g_K[BB * NN * DD];
__device__ __align__(128) float g_V[BB * NN * DD];
__device__ __align__(128) float g_X[BB * NN * DD];
__device__ __align__(128) float g_G[BB * NN * NN];

// ---------------------------------------------------------------------------
// helpers
// ---------------------------------------------------------------------------
__device__ __forceinline__ unsigned f2tf(float x) {
    unsigned r;
    asm("cvt.rna.tf32.f32 %0, %1;" : "=r"(r) : "f"(x));
    return r;
}

__device__ __forceinline__ void mma8(float* c,
                                     unsigned a0, unsigned a1, unsigned a2, unsigned a3,
                                     unsigned b0, unsigned b1) {
    asm volatile(
        "mma.sync.aligned.m16n8k8.row.col.f32.tf32.tf32.f32 "
        "{%0,%1,%2,%3},{%4,%5,%6,%7},{%8,%9},{%0,%1,%2,%3};"
        : "+f"(c[0]), "+f"(c[1]), "+f"(c[2]), "+f"(c[3])
        : "r"(a0), "r"(a1), "r"(a2), "r"(a3), "r"(b0), "r"(b1));
}

__device__ __forceinline__ void cpa16(unsigned saddr, const void* gptr) {
    asm volatile("cp.async.cg.shared.global [%0], [%1], 16;" :: "r"(saddr), "l"(gptr));
}
#define CP_COMMIT() asm volatile("cp.async.commit_group;")
#define CP_WAIT0()  asm volatile("cp.async.wait_group 0;")

// ---------------------------------------------------------------------------
// GEMM core: Y[m,n] = sum_k X[m,k]*W[n,k] + bias[n]; K = 256
// Block tile 128x64, BK=32, 256 thr = 8 warps (4m x 2n), warp tile 32x32.
// Register-prefetched K-tiles. cvt_out: store tf32 bit pattern.
// ---------------------------------------------------------------------------
#define GBM 128
#define GBN 64
#define GBK 32
#define GLD (GBK + 4)

__device__ __forceinline__ void gemm_core(
    const float* __restrict__ X, const float* __restrict__ W,
    const float* __restrict__ bias, float* __restrict__ Y,
    int cvt_out, unsigned* Xs, unsigned* Ws,
    int m0, int n0)
{
    const int tid = threadIdx.x;
    const int warp = tid >> 5, lane = tid & 31;
    const int g = lane >> 2, tig = lane & 3;
    const int wm = warp >> 1, wn = warp & 1;

    float acc[2][4][4];
#pragma unroll
    for (int mt = 0; mt < 2; mt++)
#pragma unroll
        for (int nt = 0; nt < 4; nt++)
#pragma unroll
            for (int i = 0; i < 4; i++) acc[mt][nt][i] = 0.f;

    float4 xv[4], wv[2];
#pragma unroll
    for (int i = 0; i < 4; i++) {
        int e = tid + 256 * i;
        xv[i] = *(const float4*)&X[(size_t)(m0 + (e >> 3)) * DD + 4 * (e & 7)];
    }
#pragma unroll
    for (int i = 0; i < 2; i++) {
        int e = tid + 256 * i;
        wv[i] = *(const float4*)&W[(size_t)(n0 + (e >> 3)) * DD + 4 * (e & 7)];
    }

    for (int kt = 0; kt < 8; kt++) {
        __syncthreads();
#pragma unroll
        for (int i = 0; i < 4; i++) {
            int e = tid + 256 * i;
            unsigned* p = &Xs[(e >> 3) * GLD + 4 * (e & 7)];
            p[0] = f2tf(xv[i].x); p[1] = f2tf(xv[i].y);
            p[2] = f2tf(xv[i].z); p[3] = f2tf(xv[i].w);
        }
#pragma unroll
        for (int i = 0; i < 2; i++) {
            int e = tid + 256 * i;
            unsigned* p = &Ws[(e >> 3) * GLD + 4 * (e & 7)];
            p[0] = f2tf(wv[i].x); p[1] = f2tf(wv[i].y);
            p[2] = f2tf(wv[i].z); p[3] = f2tf(wv[i].w);
        }
        __syncthreads();

        if (kt < 7) {
            int ko = (kt + 1) * GBK;
#pragma unroll
            for (int i = 0; i < 4; i++) {
                int e = tid + 256 * i;
                xv[i] = *(const float4*)&X[(size_t)(m0 + (e >> 3)) * DD + ko + 4 * (e & 7)];
            }
#pragma unroll
            for (int i = 0; i < 2; i++) {
                int e = tid + 256 * i;
                wv[i] = *(const float4*)&W[(size_t)(n0 + (e >> 3)) * DD + ko + 4 * (e & 7)];
            }
        }

#pragma unroll
        for (int k8 = 0; k8 < 4; k8++) {
            int k0 = k8 * 8;
            unsigned a[2][4];
#pragma unroll
            for (int mt = 0; mt < 2; mt++) {
                int r = wm * 32 + mt * 16;
                a[mt][0] = Xs[(r + g) * GLD + k0 + tig];
                a[mt][1] = Xs[(r + g + 8) * GLD + k0 + tig];
                a[mt][2] = Xs[(r + g) * GLD + k0 + tig + 4];
                a[mt][3] = Xs[(r + g + 8) * GLD + k0 + tig + 4];
            }
#pragma unroll
            for (int nt = 0; nt < 4; nt++) {
                int cb = wn * 32 + nt * 8;
                unsigned b0 = Ws[(cb + g) * GLD + k0 + tig];
                unsigned b1 = Ws[(cb + g) * GLD + k0 + tig + 4];
                mma8(acc[0][nt], a[0][0], a[0][1], a[0][2], a[0][3], b0, b1);
                mma8(acc[1][nt], a[1][0], a[1][1], a[1][2], a[1][3], b0, b1);
            }
        }
    }

#pragma unroll
    for (int mt = 0; mt < 2; mt++) {
        int row = m0 + wm * 32 + mt * 16 + g;
#pragma unroll
        for (int nt = 0; nt < 4; nt++) {
            int col = n0 + wn * 32 + nt * 8 + 2 * tig;
            float b0 = bias[col], b1 = bias[col + 1];
            float v00 = acc[mt][nt][0] + b0, v01 = acc[mt][nt][1] + b1;
            float v10 = acc[mt][nt][2] + b0, v11 = acc[mt][nt][3] + b1;
            if (cvt_out) {
                v00 = __uint_as_float(f2tf(v00)); v01 = __uint_as_float(f2tf(v01));
                v10 = __uint_as_float(f2tf(v10)); v11 = __uint_as_float(f2tf(v11));
            }
            *(float2*)&Y[(size_t)row * DD + col] = make_float2(v00, v01);
            *(float2*)&Y[(size_t)(row + 8) * DD + col] = make_float2(v10, v11);
        }
    }
}

// ---------------------------------------------------------------------------
// Fused launch 1: z=0/1/2 -> Q/K/V projection (tf32 out); z=3 -> build_G
// ---------------------------------------------------------------------------
__global__ void __launch_bounds__(256) fused_qkv_g(
    const float* __restrict__ query, const float* __restrict__ key_,
    const float* __restrict__ value,
    const float* __restrict__ Wq, const float* __restrict__ bq,
    const float* __restrict__ Wk, const float* __restrict__ bk,
    const float* __restrict__ Wv, const float* __restrict__ bv,
    const float* __restrict__ dist, const float* __restrict__ adj,
    const int* __restrict__ mask)
{
    __shared__ unsigned Xs[GBM * GLD];
    __shared__ unsigned Ws[GBN * GLD];
    __shared__ float redM[2][4], redS[2][4], redA[2][4];

    const int z = blockIdx.z;
    if (z < 3) {
        const float* X = (z == 0) ? query : (z == 1) ? key_ : value;
        const float* W = (z == 0) ? Wq : (z == 1) ? Wk : Wv;
        const float* bias = (z == 0) ? bq : (z == 1) ? bk : bv;
        float* Y = (z == 0) ? g_Q : (z == 1) ? g_K : g_V;
        gemm_core(X, W, bias, Y, 1, Xs, Ws, blockIdx.x * GBM, blockIdx.y * GBN);
        return;
    }

    // build_G: block id handles 32 rows (2 rows per iteration, 128 thr each)
    const int id = blockIdx.y * 64 + blockIdx.x;   // 0..255
    const int half = threadIdx.x >> 7;
    const int tl = threadIdx.x & 127;
    const int lane = threadIdx.x & 31;
    const int w4 = (threadIdx.x >> 5) & 3;
    const float NI = -3.0e38f;

    for (int it = 0; it < 16; it++) {
        int R = id * 32 + it * 2 + half;           // global row in [0, 8192)
        int b = R >> 9;
        size_t rb = (size_t)R * NN;

        float4 d = *(const float4*)&dist[rb + 4 * tl];
        float4 a = *(const float4*)&adj[rb + 4 * tl];
        int4 mv = *(const int4*)&mask[b * NN + 4 * tl];

        float s0 = mv.x ? -d.x : NI;
        float s1 = mv.y ? -d.y : NI;
        float s2 = mv.z ? -d.z : NI;
        float s3 = mv.w ? -d.w : NI;

        float mx = fmaxf(fmaxf(s0, s1), fmaxf(s2, s3));
#pragma unroll
        for (int o = 16; o > 0; o >>= 1) mx = fmaxf(mx, __shfl_xor_sync(0xffffffffu, mx, o));
        if (lane == 0) redM[half][w4] = mx;
        __syncthreads();
        float rmx = fmaxf(fmaxf(redM[half][0], redM[half][1]),
                          fmaxf(redM[half][2], redM[half][3]));

        float e0 = mv.x ? __expf(s0 - rmx) : 0.f;
        float e1 = mv.y ? __expf(s1 - rmx) : 0.f;
        float e2 = mv.z ? __expf(s2 - rmx) : 0.f;
        float e3 = mv.w ? __expf(s3 - rmx) : 0.f;
        float se = (e0 + e1) + (e2 + e3);
        float sa = (a.x + a.y) + (a.z + a.w);
#pragma unroll
        for (int o = 16; o > 0; o >>= 1) {
            se += __shfl_xor_sync(0xffffffffu, se, o);
            sa += __shfl_xor_sync(0xffffffffu, sa, o);
        }
        if (lane == 0) { redS[half][w4] = se; redA[half][w4] = sa; }
        __syncthreads();
        float tse = redS[half][0] + redS[half][1] + redS[half][2] + redS[half][3];
        float tsa = redA[half][0] + redA[half][1] + redA[half][2] + redA[half][3];

        float invd = 0.3f / tse;
        float inva = 0.4f / (tsa + 1e-6f);
        float4 o4 = make_float4(e0 * invd + a.x * inva, e1 * invd + a.y * inva,
                                e2 * invd + a.z * inva, e3 * invd + a.w * inva);
        *(float4*)&g_G[rb + 4 * tl] = o4;
    }
}

// ---------------------------------------------------------------------------
// Final projection: out = g_X @ Wo^T + bo (fp32 out)
// ---------------------------------------------------------------------------
__global__ void __launch_bounds__(256) gemm_final(
    const float* __restrict__ Wo, const float* __restrict__ bo,
    float* __restrict__ out)
{
    __shared__ unsigned Xs[GBM * GLD];
    __shared__ unsigned Ws[GBN * GLD];
    gemm_core(g_X, Wo, bo, out, 0, Xs, Ws, blockIdx.x * GBM, blockIdx.y * GBN);
}

// ---------------------------------------------------------------------------
// Fused attention. Q/K/V already tf32 bit patterns -> cp.async, no cvt.
// Phase 1: S = Q K^T -> Wsh; softmax+blend(G) -> tf32 weights in Wsh
// (V cp.async issued before softmax, waited after); Phase 2: O = W V.
// ---------------------------------------------------------------------------
#define QT 64
#define WLD (NN + 4)     // 516
#define KLD (DKK + 4)    // 36

#define SM_KV (QT * WLD)
#define SM_Q  (SM_KV + NN * KLD)
#define SM_M  (SM_Q + QT * KLD)
#define SM_TOT (SM_M + NN)
#define ATT_SMEM (SM_TOT * 4)

__global__ void __launch_bounds__(256) attn_tc(const int* __restrict__ mask)
{
    extern __shared__ unsigned sm[];
    float* Wsh = (float*)sm;         // [64][516]
    unsigned* KVs = sm + SM_KV;      // [512][36]
    unsigned* Qs = sm + SM_Q;        // [64][36]
    float* msk = (float*)(sm + SM_M);

    const int qt = blockIdx.x, h = blockIdx.y, b = blockIdx.z;
    const int q0 = qt * QT;
    const int tid = threadIdx.x, warp = tid >> 5, lane = tid & 31;
    const int g = lane >> 2, tig = lane & 3;

    unsigned sb = (unsigned)__cvta_generic_to_shared(sm);

    // Async load Q (64x32) and K (512x32) — raw tf32 bits
#pragma unroll
    for (int i = 0; i < 2; i++) {
        int e = tid + 256 * i, r = e >> 3, c = e & 7;
        cpa16(sb + 4 * (SM_Q + r * KLD + 4 * c),
              &g_Q[((size_t)(b * NN + q0 + r)) * DD + h * DKK + 4 * c]);
    }
#pragma unroll
    for (int i = 0; i < 16; i++) {
        int e = tid + 256 * i, r = e >> 3, c = e & 7;
        cpa16(sb + 4 * (SM_KV + r * KLD + 4 * c),
              &g_K[((size_t)(b * NN + r)) * DD + h * DKK + 4 * c]);
    }
    CP_COMMIT();

#pragma unroll
    for (int i = 0; i < 2; i++) {
        int k = tid + 256 * i;
        msk[k] = (mask[b * NN + k] != 0) ? 0.f : 1.f;
    }
    CP_WAIT0();
    __syncthreads();

    // Phase 1: scores
    {
        const int wm = warp >> 1, wn = warp & 1;
        unsigned a[4][4];
#pragma unroll
        for (int k8 = 0; k8 < 4; k8++) {
            int k0 = k8 * 8, r = wm * 16;
            a[k8][0] = Qs[(r + g) * KLD + k0 + tig];
            a[k8][1] = Qs[(r + g + 8) * KLD + k0 + tig];
            a[k8][2] = Qs[(r + g) * KLD + k0 + tig + 4];
            a[k8][3] = Qs[(r + g + 8) * KLD + k0 + tig + 4];
        }
#pragma unroll
        for (int nc = 0; nc < 4; nc++) {
            float acc[8][4];
#pragma unroll
            for (int nt = 0; nt < 8; nt++)
#pragma unroll
                for (int i = 0; i < 4; i++) acc[nt][i] = 0.f;
#pragma unroll
            for (int k8 = 0; k8 < 4; k8++) {
                int k0 = k8 * 8;
#pragma unroll
                for (int nt = 0; nt < 8; nt++) {
                    int key = wn * 256 + nc * 64 + nt * 8;
                    unsigned b0 = KVs[(key + g) * KLD + k0 + tig];
                    unsigned b1 = KVs[(key + g) * KLD + k0 + tig + 4];
                    mma8(acc[nt], a[k8][0], a[k8][1], a[k8][2], a[k8][3], b0, b1);
                }
            }
            int row = wm * 16 + g;
#pragma unroll
            for (int nt = 0; nt < 8; nt++) {
                int col = wn * 256 + nc * 64 + nt * 8 + 2 * tig;
                *(float2*)&Wsh[row * WLD + col] = make_float2(acc[nt][0], acc[nt][1]);
                *(float2*)&Wsh[(row + 8) * WLD + col] = make_float2(acc[nt][2], acc[nt][3]);
            }
        }
    }
    __syncthreads();

    // Issue V load (overwrites K region) — hidden behind softmax
#pragma unroll
    for (int i = 0; i < 16; i++) {
        int e = tid + 256 * i, r = e >> 3, c = e & 7;
        cpa16(sb + 4 * (SM_KV + r * KLD + 4 * c),
              &g_V[((size_t)(b * NN + r)) * DD + h * DKK + 4 * c]);
    }
    CP_COMMIT();

    // Softmax + blend with G (warp w handles rows w*8..w*8+7)
    const float scale = 0.17677669529663687f;  // 1/sqrt(32)
    for (int rr = 0; rr < 8; rr++) {
        int row = warp * 8 + rr;
        float v[16];
        float m = -3.4e38f;
#pragma unroll
        for (int j = 0; j < 16; j++) {
            int k = lane + 32 * j;
            float s = Wsh[row * WLD + k] * scale - 1e12f * msk[k];
            v[j] = s;
            m = fmaxf(m, s);
        }
#pragma unroll
        for (int o = 16; o > 0; o >>= 1) m = fmaxf(m, __shfl_xor_sync(0xffffffffu, m, o));
        float sum = 0.f;
#pragma unroll
        for (int j = 0; j < 16; j++) {
            float e = __expf(v[j] - m);
            v[j] = e;
            sum += e;
        }
#pragma unroll
        for (int o = 16; o > 0; o >>= 1) sum += __shfl_xor_sync(0xffffffffu, sum, o);
        float inv = 0.3f / sum;
        const float* Grow = g_G + ((size_t)(b * NN + q0 + row)) * NN;
#pragma unroll
        for (int j = 0; j < 16; j++) {
            int k = lane + 32 * j;
            float w = fmaf(v[j], inv, Grow[k]);
            ((unsigned*)Wsh)[row * WLD + k] = f2tf(w);
        }
    }
    CP_WAIT0();
    __syncthreads();

    // Phase 2: O = W @ V
    {
        const int wm = warp >> 1, wn = warp & 1;
        const unsigned* W32 = (const unsigned*)Wsh;
        float o[2][4];
#pragma unroll
        for (int nt = 0; nt < 2; nt++)
#pragma unroll
            for (int i = 0; i < 4; i++) o[nt][i] = 0.f;

#pragma unroll 4
        for (int k0 = 0; k0 < NN; k0 += 8) {
            int r = wm * 16;
            unsigned a0 = W32[(r + g) * WLD + k0 + tig];
            unsigned a1 = W32[(r + g + 8) * WLD + k0 + tig];
            unsigned a2 = W32[(r + g) * WLD + k0 + tig + 4];
            unsigned a3 = W32[(r + g + 8) * WLD + k0 + tig + 4];
#pragma unroll
            for (int nt = 0; nt < 2; nt++) {
                int n = wn * 16 + nt * 8;
                unsigned b0 = KVs[(k0 + tig) * KLD + n + g];
                unsigned b1 = KVs[(k0 + tig + 4) * KLD + n + g];
                mma8(o[nt], a0, a1, a2, a3, b0, b1);
            }
        }
        int row = q0 + wm * 16 + g;
#pragma unroll
        for (int nt = 0; nt < 2; nt++) {
            int col = h * DKK + wn * 16 + nt * 8 + 2 * tig;
            *(float2*)&g_X[((size_t)(b * NN + row)) * DD + col] = make_float2(o[nt][0], o[nt][1]);
            *(float2*)&g_X[((size_t)(b * NN + row + 8)) * DD + col] = make_float2(o[nt][2], o[nt][3]);
        }
    }
}

// ---------------------------------------------------------------------------
// Launch. Inputs: query,key,value,adj,dist,edges_att,mask,Wq,bq,Wk,bk,Wv,bv,Wo,bo
// ---------------------------------------------------------------------------
extern "C" void kernel_launch(void* const* d_in, const int* in_sizes, int n_in,
                              void* d_out, int out_size)
{
    (void)in_sizes; (void)n_in; (void)out_size;
    const float* query = (const float*)d_in[0];
    const float* key_  = (const float*)d_in[1];
    const float* value = (const float*)d_in[2];
    const float* adj   = (const float*)d_in[3];
    const float* dist  = (const float*)d_in[4];
    const int*   mask  = (const int*)d_in[6];
    const float* Wq = (const float*)d_in[7],  *bq = (const float*)d_in[8];
    const float* Wk = (const float*)d_in[9],  *bk = (const float*)d_in[10];
    const float* Wv = (const float*)d_in[11], *bv = (const float*)d_in[12];
    const float* Wo = (const float*)d_in[13], *bo = (const float*)d_in[14];
    float* out = (float*)d_out;

    cudaFuncSetAttribute(attn_tc, cudaFuncAttributeMaxDynamicSharedMemorySize, ATT_SMEM);

    fused_qkv_g<<<dim3(BB * NN / GBM, DD / GBN, 4), 256>>>(
        query, key_, value, Wq, bq, Wk, bk, Wv, bv, dist, adj, mask);

    attn_tc<<<dim3(NN / QT, HH, BB), 256, ATT_SMEM>>>(mask);

    gemm_final<<<dim3(BB * NN / GBM, DD / GBN), 256>>>(Wo, bo, out);
}